// round 6
// baseline (speedup 1.0000x reference)
#include <cuda_runtime.h>

#define H 512
#define W 512
#define NPTS 12
#define NMAPS 16          // B(8) * 2 groups
#define TSAT 21.0f        // d >= TSAT -> tanh(2*sqrt(d)) == 1.0f exactly in fp32
#define PRAD 23           // patch radius in pixels
#define PROWS 47          // 2*PRAD + 1
#define PCOL4 13          // float4 columns per patch (52 px, alignment slack)
#define NPATCH_BLK (NMAPS * NPTS * 2)   // 384: 2 blocks per patch (row halves)
#define NFILL_BLK (NMAPS * H)           // 8192: one row each

// ---- packed fp32 helpers ----
__device__ __forceinline__ unsigned long long f32x2_add(unsigned long long a, unsigned long long b) {
    unsigned long long r;
    asm("add.rn.f32x2 %0, %1, %2;" : "=l"(r) : "l"(a), "l"(b));
    return r;
}
__device__ __forceinline__ unsigned long long f32x2_fma(unsigned long long a, unsigned long long b, unsigned long long c) {
    unsigned long long r;
    asm("fma.rn.f32x2 %0, %1, %2, %3;" : "=l"(r) : "l"(a), "l"(b), "l"(c));
    return r;
}
__device__ __forceinline__ unsigned long long pack2(float lo, float hi) {
    unsigned long long r;
    asm("mov.b64 %0, {%1, %2};" : "=l"(r) : "f"(lo), "f"(hi));
    return r;
}
__device__ __forceinline__ void unpack2(unsigned long long v, float& lo, float& hi) {
    asm("mov.b64 {%0, %1}, %2;" : "=f"(lo), "=f"(hi) : "l"(v));
}

// tanh(2*sqrt(d)) = 1 - 2/(exp(4*sqrt(d)) + 1); only called with d < TSAT.
__device__ __forceinline__ float fast_out(float d) {
    float s, t, r;
    asm("sqrt.approx.f32 %0, %1;" : "=f"(s) : "f"(d));
    float e = 5.770780163555852f * s;          // 4*log2(e)*sqrt(d)
    asm("ex2.approx.f32 %0, %1;" : "=f"(t) : "f"(e));
    float tp1 = t + 1.0f;
    asm("rcp.approx.f32 %0, %1;" : "=f"(r) : "f"(tp1));
    return fmaf(-2.0f, r, 1.0f);
}

// Single fused kernel. Blocks [0, 384): patch compute. Blocks [384, 8576): fill.
// Fill skips EXACTLY the float4 columns that patch blocks write (identical
// integer bbox arithmetic) -> disjoint writes, no ordering needed.
__global__ __launch_bounds__(128) void distmaps_fused(
    const float* __restrict__ coords,   // (8, 24, 3)
    float* __restrict__ out)            // (8, 2, 512, 512)
{
    const int b   = blockIdx.x;
    const int tid = threadIdx.x;

    __shared__ float s_y[NPTS];
    __shared__ float s_nx[NPTS];     // -x * 0.2
    __shared__ float s_base[NPTS];   // 0 valid, 1e6 invalid
    __shared__ int   s_ir0[NPTS];    // bbox first row
    __shared__ int   s_ifb[NPTS];    // bbox first float4 column
    __shared__ int   s_fbl[NPTS];    // compacted active fb list (fill path)
    __shared__ int   s_cnt;

    if (b < NPATCH_BLK) {
        // ---------------- patch block ----------------
        const int pid  = b >> 1;
        const int half = b & 1;
        const int m = pid / NPTS;
        const int p = pid % NPTS;

        if (tid < NPTS) {
            const float* q = coords + (m * NPTS + tid) * 3;
            float y = q[0];
            float x = q[1];
            bool invalid = fmaxf(y, x) < 0.0f;
            s_y[tid]    = y;
            s_nx[tid]   = -x * 0.2f;
            s_base[tid] = invalid ? 1000000.0f : 0.0f;
            s_ir0[tid]  = (int)floorf(y) - PRAD;
            s_ifb[tid]  = (((int)floorf(x) - PRAD) & ~3) >> 2;
        }
        __syncthreads();

        if (s_base[p] != 0.0f) return;          // invalid anchor: no patch

        const int rbeg  = s_ir0[p] + half * 24;
        const int nrows = half ? (PROWS - 24) : 24;
        const int fb    = s_ifb[p];
        const int units = nrows * PCOL4;

        for (int u = tid; u < units; u += 128) {
            const int r = rbeg + u / PCOL4;
            const int c = (fb + u % PCOL4) * 4;
            if (r < 0 || r >= H || c < 0 || c > W - 4) continue;

            const float rf = (float)r;
            unsigned long long cs0 = pack2((float)c * 0.2f,       (float)(c + 1) * 0.2f);
            unsigned long long cs1 = pack2((float)(c + 2) * 0.2f, (float)(c + 3) * 0.2f);

            float m0 = 1.0e6f, m1 = 1.0e6f, m2 = 1.0e6f, m3 = 1.0e6f;
#pragma unroll
            for (int j = 0; j < NPTS; j++) {
                float t = (rf - s_y[j]) * 0.2f;
                float a = fmaf(t, t, s_base[j]);
                unsigned long long nxv = pack2(s_nx[j], s_nx[j]);
                unsigned long long av  = pack2(a, a);
                unsigned long long dc, d;
                float d0, d1;
                dc = f32x2_add(cs0, nxv); d = f32x2_fma(dc, dc, av);
                unpack2(d, d0, d1); m0 = fminf(m0, d0); m1 = fminf(m1, d1);
                dc = f32x2_add(cs1, nxv); d = f32x2_fma(dc, dc, av);
                unpack2(d, d0, d1); m2 = fminf(m2, d0); m3 = fminf(m3, d1);
            }

            float4 v;
            v.x = (m0 < TSAT) ? fast_out(m0) : 1.0f;
            v.y = (m1 < TSAT) ? fast_out(m1) : 1.0f;
            v.z = (m2 < TSAT) ? fast_out(m2) : 1.0f;
            v.w = (m3 < TSAT) ? fast_out(m3) : 1.0f;

            *(float4*)(out + ((size_t)m * H + r) * W + c) = v;
        }
    } else {
        // ---------------- fill block: one row ----------------
        const int fbk = b - NPATCH_BLK;
        const int m   = fbk >> 9;       // /512
        const int row = fbk & 511;

        if (tid == 0) s_cnt = 0;
        __syncthreads();

        if (tid < NPTS) {
            const float* q = coords + (m * NPTS + tid) * 3;
            float y = q[0];
            float x = q[1];
            bool valid = fmaxf(y, x) >= 0.0f;
            int ir0 = (int)floorf(y) - PRAD;
            if (valid && (unsigned)(row - ir0) <= (unsigned)(PROWS - 1)) {
                int pos = atomicAdd(&s_cnt, 1);
                s_fbl[pos] = (((int)floorf(x) - PRAD) & ~3) >> 2;
            }
        }
        __syncthreads();

        const int cnt = s_cnt;
        bool skip = false;
        for (int e = 0; e < cnt; e++)
            skip |= (unsigned)(tid - s_fbl[e]) <= (unsigned)(PCOL4 - 1);

        if (!skip) {
            float4* orow = (float4*)(out + ((size_t)m * H + row) * W);
            orow[tid] = make_float4(1.0f, 1.0f, 1.0f, 1.0f);
        }
    }
}

extern "C" void kernel_launch(void* const* d_in, const int* in_sizes, int n_in,
                              void* d_out, int out_size)
{
    const float* coords = nullptr;
    for (int i = 0; i < n_in; i++) {
        if (in_sizes[i] == 8 * 24 * 3) { coords = (const float*)d_in[i]; break; }
    }
    if (!coords) coords = (const float*)d_in[n_in - 1];

    float* out = (float*)d_out;

    distmaps_fused<<<NPATCH_BLK + NFILL_BLK, 128>>>(coords, out);
}